// round 2
// baseline (speedup 1.0000x reference)
#include <cuda_runtime.h>

// HEALPix p=1 padding: x (24,128,128,128) f32 -> y (24,128,130,130) f32
// Plane P in [0,3072). Face F = (P>>7) % 12.

#define NN 128
#define NP 130
#define PLANE_IN  (NN*NN)          // 16384
#define PLANE_OUT (NP*NP)          // 16900
#define FACE_DELTA (128*PLANE_IN)  // 2097152
#define NPLANES 3072

// Per-face neighbor table: t, tl, lft, bl, b, br, rgt, tr
__constant__ int NBT[12][8] = {
    {1, 2, 3, 3, 4, 8, 5, 1},      // F0  north
    {2, 3, 0, 0, 5, 9, 6, 2},      // F1
    {3, 0, 1, 1, 6, 10, 7, 3},     // F2
    {0, 1, 2, 2, 7, 11, 4, 0},     // F3
    {0, -1, 3, 7, 11, -1, 8, 5},   // F4  equatorial
    {1, -1, 0, 4, 8, -1, 9, 6},    // F5
    {2, -1, 1, 5, 9, -1, 10, 7},   // F6
    {3, -1, 2, 6, 10, -1, 11, 4},  // F7
    {5, 0, 4, 11, 11, 10, 9, 9},   // F8  south
    {6, 1, 5, 8, 8, 11, 10, 10},   // F9
    {7, 2, 6, 9, 9, 8, 11, 11},    // F10
    {4, 3, 7, 10, 10, 9, 8, 8},    // F11
};

// ---------------- interior rows: one block per plane, 8 warps x 16 rows ----------------
__global__ void __launch_bounds__(256) healpix_interior_kernel(
    const float* __restrict__ x, float* __restrict__ y)
{
    int P    = blockIdx.x;
    int warp = threadIdx.x >> 5;
    int lane = threadIdx.x & 31;
    int F    = (P >> 7) % 12;
    int ty   = F >> 2;             // 0=north, 1=equatorial, 2=south

    const float* __restrict__ xin = x + (long)P * PLANE_IN;
    float* __restrict__ yout      = y + (long)P * PLANE_OUT;

    int lft_b = (NBT[F][2] - F) * FACE_DELTA;   // relative to plane base
    int rgt_b = (NBT[F][6] - F) * FACE_DELTA;

    int ir0 = warp * 16;

    #pragma unroll 4
    for (int k = 0; k < 16; ++k) {
        int ir = ir0 + k;                       // input row 0..127
        int r  = ir + 1;                        // output row 1..128
        const float* inrow = xin + ir * NN;

        float4 f4 = *reinterpret_cast<const float4*>(inrow + 4 * lane);

        float lh = 0.0f, rh = 0.0f;
        if (lane == 0)
            lh = xin[(ty == 0) ? (lft_b + ir) : (lft_b + ir * NN + (NN - 1))];
        if (lane == 31)
            rh = xin[(ty == 2) ? (rgt_b + (NN - 1) * NN + ir) : (rgt_b + ir * NN)];

        float* outrow = yout + r * NP;

        if (r & 1) {
            // odd r: 16B-aligned chunks at cols [4k+2 .. 4k+5]
            float s = __shfl_down_sync(0xffffffffu, f4.x, 1);   // in[4*lane+4]
            if (lane == 31) s = rh;
            *reinterpret_cast<float4*>(outrow + 4 * lane + 2) =
                make_float4(f4.y, f4.z, f4.w, s);
            if (lane == 0) { outrow[0] = lh; outrow[1] = f4.x; }
        } else {
            // even r: 16B-aligned chunks at cols [4k .. 4k+3]
            float s = __shfl_up_sync(0xffffffffu, f4.w, 1);     // in[4*lane-1]
            if (lane == 0) s = lh;
            *reinterpret_cast<float4*>(outrow + 4 * lane) =
                make_float4(s, f4.x, f4.y, f4.z);
            if (lane == 31) { outrow[128] = f4.w; outrow[129] = rh; }
        }
    }
}

// ---------------- halo rows (r = 0 and 129): one warp per row ----------------
__global__ void __launch_bounds__(256) healpix_halo_kernel(
    const float* __restrict__ x, float* __restrict__ y)
{
    int gt   = blockIdx.x * blockDim.x + threadIdx.x;
    int w    = gt >> 5;
    int lane = gt & 31;
    if (w >= NPLANES * 2) return;

    int P  = w >> 1;
    int r  = (w & 1) ? (NP - 1) : 0;
    int F  = (P >> 7) % 12;
    int ty = F >> 2;

    long inb = (long)P * PLANE_IN;
    float* outrow = y + (long)P * PLANE_OUT + r * NP;

    if (r == 0) {
        int tbase = (int)0 + (NBT[F][0] - F) * FACE_DELTA;
        #pragma unroll
        for (int j = lane; j < NP; j += 32) {
            float v;
            if (j == 0) {
                if (ty == 0) {
                    v = x[inb + (NBT[F][1] - F) * FACE_DELTA];              // tl[0,0]
                } else if (ty == 1) {
                    int lb = (NBT[F][2] - F) * FACE_DELTA;
                    v = 0.5f * x[inb + tbase + (NN - 1) * NN]               // t[127,0]
                      + 0.5f * x[inb + lb + (NN - 1)];                      // lft[0,127]
                } else {
                    v = x[inb + (NBT[F][1] - F) * FACE_DELTA
                          + (NN - 1) * NN + (NN - 1)];                      // tl[127,127]
                }
            } else if (j == NP - 1) {
                v = x[inb + (NBT[F][7] - F) * FACE_DELTA + (NN - 1) * NN];  // tr[127,0]
            } else {
                int jj = j - 1;
                v = (ty == 0) ? x[inb + tbase + jj * NN]                    // t[jj,0]
                              : x[inb + tbase + (NN - 1) * NN + jj];        // t[127,jj]
            }
            outrow[j] = v;
        }
    } else {
        int bbase = (NBT[F][4] - F) * FACE_DELTA;
        #pragma unroll
        for (int j = lane; j < NP; j += 32) {
            float v;
            if (j == 0) {
                v = x[inb + (NBT[F][3] - F) * FACE_DELTA + (NN - 1)];       // bl[0,127]
            } else if (j == NP - 1) {
                if (ty == 0) {
                    v = x[inb + (NBT[F][5] - F) * FACE_DELTA];              // br[0,0]
                } else if (ty == 1) {
                    int rb = (NBT[F][6] - F) * FACE_DELTA;
                    v = 0.5f * x[inb + bbase + (NN - 1)]                    // b[0,127]
                      + 0.5f * x[inb + rb + (NN - 1) * NN];                 // rgt[127,0]
                } else {
                    v = x[inb + (NBT[F][5] - F) * FACE_DELTA
                          + (NN - 1) * NN + (NN - 1)];                      // br[127,127]
                }
            } else {
                int jj = j - 1;
                v = (ty == 2) ? x[inb + bbase + jj * NN + (NN - 1)]         // b[jj,127]
                              : x[inb + bbase + jj];                        // b[0,jj]
            }
            outrow[j] = v;
        }
    }
}

extern "C" void kernel_launch(void* const* d_in, const int* in_sizes, int n_in,
                              void* d_out, int out_size)
{
    const float* x = (const float*)d_in[0];
    float* y = (float*)d_out;

    healpix_interior_kernel<<<NPLANES, 256>>>(x, y);

    int halo_warps = NPLANES * 2;                        // 6144
    int halo_threads = halo_warps * 32;                  // 196608
    healpix_halo_kernel<<<(halo_threads + 255) / 256, 256>>>(x, y);
}

// round 3
// speedup vs baseline: 1.1478x; 1.1478x over previous
#include <cuda_runtime.h>

// HEALPix p=1 padding: x (24,128,128,128) f32 -> y (24,128,130,130) f32
// One launch: blocks [0,3072) do interior rows of one plane each;
// blocks [3072,3840) do halo rows (8 warps/block, 1 halo row per warp).

#define NN 128
#define NP 130
#define PLANE_IN  (NN*NN)          // 16384
#define PLANE_OUT (NP*NP)          // 16900
#define FACE_DELTA (128*PLANE_IN)  // 2097152
#define NPLANES 3072
#define INT_BLOCKS NPLANES
#define HALO_BLOCKS ((NPLANES*2)/8)   // 768

// Per-face neighbor table: t, tl, lft, bl, b, br, rgt, tr
__constant__ int NBT[12][8] = {
    {1, 2, 3, 3, 4, 8, 5, 1},      // F0  north
    {2, 3, 0, 0, 5, 9, 6, 2},      // F1
    {3, 0, 1, 1, 6, 10, 7, 3},     // F2
    {0, 1, 2, 2, 7, 11, 4, 0},     // F3
    {0, -1, 3, 7, 11, -1, 8, 5},   // F4  equatorial
    {1, -1, 0, 4, 8, -1, 9, 6},    // F5
    {2, -1, 1, 5, 9, -1, 10, 7},   // F6
    {3, -1, 2, 6, 10, -1, 11, 4},  // F7
    {5, 0, 4, 11, 11, 10, 9, 9},   // F8  south
    {6, 1, 5, 8, 8, 11, 10, 10},   // F9
    {7, 2, 6, 9, 9, 8, 11, 11},    // F10
    {4, 3, 7, 10, 10, 9, 8, 8},    // F11
};

__global__ void __launch_bounds__(256) healpix_pad_kernel(
    const float* __restrict__ x, float* __restrict__ y)
{
    if (blockIdx.x < INT_BLOCKS) {
        // ================= interior rows: one plane per block =================
        __shared__ float sl[NN];   // left edge value per input row
        __shared__ float sr[NN];   // right edge value per input row

        int P    = blockIdx.x;
        int tid  = threadIdx.x;
        int warp = tid >> 5;
        int lane = tid & 31;
        int F    = (P >> 7) % 12;
        int ty   = F >> 2;         // 0=north, 1=equatorial, 2=south

        const float* __restrict__ xin = x + (long)P * PLANE_IN;
        float* __restrict__ yout      = y + (long)P * PLANE_OUT;

        int lft_b = (NBT[F][2] - F) * FACE_DELTA;
        int rgt_b = (NBT[F][6] - F) * FACE_DELTA;

        // stage edge columns: 128 threads each side, all loads in flight at once
        if (tid < NN) {
            int ir = tid;
            sl[ir] = xin[(ty == 0) ? (lft_b + ir) : (lft_b + ir * NN + (NN - 1))];
        } else {
            int ir = tid - NN;
            sr[ir] = xin[(ty == 2) ? (rgt_b + (NN - 1) * NN + ir) : (rgt_b + ir * NN)];
        }
        __syncthreads();

        int ir0 = warp * 16;
        #pragma unroll 4
        for (int k = 0; k < 16; ++k) {
            int ir = ir0 + k;                   // input row 0..127
            int r  = ir + 1;                    // output row 1..128
            const float* inrow = xin + ir * NN;

            float4 f4 = *reinterpret_cast<const float4*>(inrow + 4 * lane);
            float lh = sl[ir];                  // broadcast LDS
            float rh = sr[ir];

            float* outrow = yout + r * NP;

            if (r & 1) {
                // odd r: aligned 16B chunks at cols [4k+2 .. 4k+5]
                float s = __shfl_down_sync(0xffffffffu, f4.x, 1);  // in[4*lane+4]
                if (lane == 31) s = rh;
                *reinterpret_cast<float4*>(outrow + 4 * lane + 2) =
                    make_float4(f4.y, f4.z, f4.w, s);
                if (lane == 0) { outrow[0] = lh; outrow[1] = f4.x; }
            } else {
                // even r: aligned 16B chunks at cols [4k .. 4k+3]
                float s = __shfl_up_sync(0xffffffffu, f4.w, 1);    // in[4*lane-1]
                if (lane == 0) s = lh;
                *reinterpret_cast<float4*>(outrow + 4 * lane) =
                    make_float4(s, f4.x, f4.y, f4.z);
                if (lane == 31) { outrow[128] = f4.w; outrow[129] = rh; }
            }
        }
    } else {
        // ================= halo rows: 1 warp per row =================
        int hb   = blockIdx.x - INT_BLOCKS;
        int warp = threadIdx.x >> 5;
        int lane = threadIdx.x & 31;
        int w    = hb * 8 + warp;              // 0..6143
        int P    = w >> 1;
        int r    = (w & 1) ? (NP - 1) : 0;
        int F    = (P >> 7) % 12;
        int ty   = F >> 2;

        long inb = (long)P * PLANE_IN;
        float* outrow = y + (long)P * PLANE_OUT + r * NP;

        if (r == 0) {
            int tbase = (NBT[F][0] - F) * FACE_DELTA;
            #pragma unroll
            for (int j = lane; j < NP; j += 32) {
                float v;
                if (j == 0) {
                    if (ty == 0) {
                        v = x[inb + (NBT[F][1] - F) * FACE_DELTA];              // tl[0,0]
                    } else if (ty == 1) {
                        int lb = (NBT[F][2] - F) * FACE_DELTA;
                        v = 0.5f * x[inb + tbase + (NN - 1) * NN]               // t[127,0]
                          + 0.5f * x[inb + lb + (NN - 1)];                      // lft[0,127]
                    } else {
                        v = x[inb + (NBT[F][1] - F) * FACE_DELTA
                              + (NN - 1) * NN + (NN - 1)];                      // tl[127,127]
                    }
                } else if (j == NP - 1) {
                    v = x[inb + (NBT[F][7] - F) * FACE_DELTA + (NN - 1) * NN];  // tr[127,0]
                } else {
                    int jj = j - 1;
                    v = (ty == 0) ? x[inb + tbase + jj * NN]                    // t[jj,0]
                                  : x[inb + tbase + (NN - 1) * NN + jj];        // t[127,jj]
                }
                outrow[j] = v;
            }
        } else {
            int bbase = (NBT[F][4] - F) * FACE_DELTA;
            #pragma unroll
            for (int j = lane; j < NP; j += 32) {
                float v;
                if (j == 0) {
                    v = x[inb + (NBT[F][3] - F) * FACE_DELTA + (NN - 1)];       // bl[0,127]
                } else if (j == NP - 1) {
                    if (ty == 0) {
                        v = x[inb + (NBT[F][5] - F) * FACE_DELTA];              // br[0,0]
                    } else if (ty == 1) {
                        int rb = (NBT[F][6] - F) * FACE_DELTA;
                        v = 0.5f * x[inb + bbase + (NN - 1)]                    // b[0,127]
                          + 0.5f * x[inb + rb + (NN - 1) * NN];                 // rgt[127,0]
                    } else {
                        v = x[inb + (NBT[F][5] - F) * FACE_DELTA
                              + (NN - 1) * NN + (NN - 1)];                      // br[127,127]
                    }
                } else {
                    int jj = j - 1;
                    v = (ty == 2) ? x[inb + bbase + jj * NN + (NN - 1)]         // b[jj,127]
                                  : x[inb + bbase + jj];                        // b[0,jj]
                }
                outrow[j] = v;
            }
        }
    }
}

extern "C" void kernel_launch(void* const* d_in, const int* in_sizes, int n_in,
                              void* d_out, int out_size)
{
    const float* x = (const float*)d_in[0];
    float* y = (float*)d_out;
    healpix_pad_kernel<<<INT_BLOCKS + HALO_BLOCKS, 256>>>(x, y);
}